// round 14
// baseline (speedup 1.0000x reference)
#include <cuda_runtime.h>

// Problem constants (fixed by setup_inputs)
#define BS      16
#define NQ      100
#define JD      51
#define ITILE   12          // rows of the cost matrix per block
#define HALF    3           // i-rows per thread sub-group (4 subs x 3 = 12)
#define NTILES  9           // ceil(100/12) -> 9*16 = 144 blocks (one wave on 148 SMs)
#define THREADS 512
#define SPITCH  52          // shared pred row pitch (52*4 = 208 B, 16B aligned)
#define TARF4   ((NQ * JD) / 4)   // 5100 floats = 1275 float4 (exact)

__global__ __launch_bounds__(THREADS)
void hungarian_cost_kernel(
    const float* __restrict__ pred_conf,    // (16,100,1)
    const float* __restrict__ pred_joint,   // (16,100,51)
    const float* __restrict__ pred_action,  // (16,100,8)
    const float* __restrict__ pred_ident,   // (16,100,10)
    const float* __restrict__ tar_conf,     // (16,100)
    const float* __restrict__ tar_joint,    // (16,100,51)
    float* __restrict__ out)                // (16,100,100)
{
    __shared__ __align__(16) float s_tar[NQ * JD];       // 20400 B, pitch 51 (odd -> LDS conflict-free)
    __shared__ __align__(16) float s_pred[ITILE * SPITCH];
    __shared__ float sA[ITILE];   // log p - log(1-p)
    __shared__ float sB[ITILE];   // log(1-p)
    __shared__ float sRC[ITILE];  // ce_action + ce_identity

    const int b    = blockIdx.y;
    const int i0   = blockIdx.x * ITILE;
    const int rows = min(ITILE, NQ - i0);
    const int tid  = threadIdx.x;
    const int j    = tid & 127;          // 0..127 (j >= 100 lanes are main-idle)
    const int sub  = tid >> 7;           // 0..3

    // ---- bulk coalesced staging FIRST so the LDGs overlap everything ----
    {
        const float4* g4 = reinterpret_cast<const float4*>(tar_joint + b * NQ * JD);
        float4* s4 = reinterpret_cast<float4*>(s_tar);
        #pragma unroll
        for (int i = tid; i < TARF4; i += THREADS)   // <=3 float4 per thread, fully coalesced
            s4[i] = g4[i];
    }
    // pred_joint tile into shared (coalesced scalar), pitch 52 for float4 inner loop
    for (int idx = tid; idx < rows * JD; idx += THREADS) {
        const int ii = idx / JD;
        const int k  = idx - ii * JD;
        s_pred[ii * SPITCH + k] = pred_joint[(b * NQ + i0) * JD + idx];
    }

    // ---- constants inputs: issue the LDGs NOW (latency overlaps staging).
    // Assigned to lanes j=100..111 of sub 0 (idle for the main compute).
    const bool is_const = (tid >= 100) && (tid < 100 + ITILE) && (tid - 100 < rows);
    const int  crow     = tid - 100;
    float cx = 0.f, ca[8], cc[10];
    if (is_const) {
        const int n = b * NQ + i0 + crow;
        cx = pred_conf[n];
        const float* a = pred_action + n * 8;
        #pragma unroll
        for (int k = 0; k < 8; k++) ca[k] = a[k];
        const float* c = pred_ident + n * 10;
        #pragma unroll
        for (int k = 0; k < 10; k++) cc[k] = c[k];
    }
    // tar_conf for the epilogue (coalesced, in-flight early)
    float tj = 0.f;
    if (j < NQ) tj = tar_conf[b * NQ + j];

    __syncthreads();    // shared tiles ready; constants chain NOT on this barrier

    // ---- constants math runs CONCURRENTLY with the main loop (idle lanes) ----
    if (is_const) {
        // stable log-sigmoid pair: log p = -log1p(e^-x), log(1-p) = -log1p(e^x)
        const float logp   = -log1pf(expf(-cx));
        const float log1mp = -log1pf(expf(cx));

        float m = ca[0];
        #pragma unroll
        for (int k = 1; k < 8; k++) m = fmaxf(m, ca[k]);
        float s = 0.f;
        #pragma unroll
        for (int k = 0; k < 8; k++) s += expf(ca[k] - m);
        const float cea = m + logf(s) - ca[0];

        float m2 = cc[0];
        #pragma unroll
        for (int k = 1; k < 10; k++) m2 = fmaxf(m2, cc[k]);
        float s2 = 0.f;
        #pragma unroll
        for (int k = 0; k < 10; k++) s2 += expf(cc[k] - m2);
        const float cei = m2 + logf(s2) - cc[0];

        sA[crow]  = logp - log1mp;
        sB[crow]  = log1mp;
        sRC[crow] = cea + cei;
    }

    // ---- main compute: joint distances accumulated into registers ----
    float joint[HALF];
    if (j < NQ) {
        // tar_joint row: shared -> registers. Addresses j*51+k: stride 51 words
        // across lanes, gcd(51,32)=1 -> bank-conflict-free scalar LDS.
        float r[JD];
        const float* srow = s_tar + j * JD;
        #pragma unroll
        for (int k = 0; k < JD; k++) r[k] = srow[k];

        #pragma unroll
        for (int h = 0; h < HALF; h++) {
            const int ii = sub * HALF + h;
            if (ii < rows) {
                const float4* row4 = reinterpret_cast<const float4*>(s_pred + ii * SPITCH);
                float a0 = 0.f, a1 = 0.f, a2 = 0.f, a3 = 0.f;
                #pragma unroll
                for (int q = 0; q < 12; q++) {      // 48 of 51 elements, LDS.128 broadcast
                    const float4 v = row4[q];
                    a0 += fabsf(r[4 * q + 0] - v.x);
                    a1 += fabsf(r[4 * q + 1] - v.y);
                    a2 += fabsf(r[4 * q + 2] - v.z);
                    a3 += fabsf(r[4 * q + 3] - v.w);
                }
                a0 += fabsf(r[48] - s_pred[ii * SPITCH + 48]);
                a1 += fabsf(r[49] - s_pred[ii * SPITCH + 49]);
                a2 += fabsf(r[50] - s_pred[ii * SPITCH + 50]);
                joint[h] = (a0 + a1) + (a2 + a3);
            } else {
                joint[h] = 0.f;
            }
        }
    }

    __syncthreads();    // constants now ready

    // ---- epilogue: apply per-row constants, store (j-coalesced) ----
    if (j < NQ) {
        #pragma unroll
        for (int h = 0; h < HALF; h++) {
            const int ii = sub * HALF + h;
            if (ii < rows) {
                // cost = rc + joint - ( B + t*A )   [== rc + joint + C_prob]
                const float res = sRC[ii] + joint[h] - sB[ii] - tj * sA[ii];
                out[(b * NQ + i0 + ii) * NQ + j] = res;
            }
        }
    }
}

extern "C" void kernel_launch(void* const* d_in, const int* in_sizes, int n_in,
                              void* d_out, int out_size)
{
    (void)in_sizes; (void)n_in; (void)out_size;
    const dim3 grid(NTILES, BS);
    hungarian_cost_kernel<<<grid, THREADS>>>(
        (const float*)d_in[0],   // pred_conf
        (const float*)d_in[1],   // pred_joint
        (const float*)d_in[2],   // pred_action
        (const float*)d_in[3],   // pred_identity
        (const float*)d_in[4],   // tar_conf
        (const float*)d_in[5],   // tar_joint
        (float*)d_out);
    // d_in[6] (tar_action) and d_in[7] (tar_identity) are unused by the
    // reference (it takes log_softmax[:, 0], not a gather).
}